// round 1
// baseline (speedup 1.0000x reference)
#include <cuda_runtime.h>
#include <math_constants.h>

#define B_PAT 4096
#define N_DIS 10000
#define DIM   256
#define BM    64            // patients per CTA tile
#define NK    32            // disease-node chunk staged in smem
#define NS    16            // N splits
#define NPER  (N_DIS / NS)  // 625
#define PT    (B_PAT / BM)  // 64 patient tiles
#define LEAKY 0.2f

// ---------------- scratch (static device globals; no allocation) ----------------
__device__ float        g_sp[B_PAT];
__device__ float        g_sn[N_DIS];
__device__ unsigned int g_max_enc;
__device__ float        g_num[NS][B_PAT][DIM];   // 67 MB partial numerators
__device__ float        g_den[NS][B_PAT];
__device__ float        g_invden[B_PAT];

// monotonic float<->uint encoding for atomicMax over signed floats
__device__ __forceinline__ unsigned enc_f(float f) {
    unsigned u = __float_as_uint(f);
    return (u & 0x80000000u) ? ~u : (u | 0x80000000u);
}
__device__ __forceinline__ float dec_f(unsigned e) {
    return __uint_as_float((e & 0x80000000u) ? (e ^ 0x80000000u) : ~e);
}

__device__ __forceinline__ float lrelu(float s) {
    return (s >= 0.0f) ? s : LEAKY * s;
}

// ---------------- kernel 0: reset global max ----------------
__global__ void k_init() { g_max_enc = 0u; }

// ---------------- kernel 1: sp, sn dot products + max(sn) ----------------
// one warp per row; rows [0,B) = patients (Wp), rows [B, B+N) = disease (Wn)
__global__ __launch_bounds__(256) void k_scores(
    const float* __restrict__ pf, const float* __restrict__ dn,
    const float* __restrict__ ak)
{
    int tid  = threadIdx.x;
    int lane = tid & 31;
    int gw   = blockIdx.x * 8 + (tid >> 5);

    float v = 0.0f;
    bool isn = false;
    if (gw < B_PAT) {
        const float4* r = (const float4*)(pf + (size_t)gw * DIM);
        const float4* w = (const float4*)ak;               // Wp
        #pragma unroll
        for (int k = 0; k < 2; k++) {
            float4 x  = r[lane * 2 + k];
            float4 ww = __ldg(&w[lane * 2 + k]);
            v += x.x * ww.x + x.y * ww.y + x.z * ww.z + x.w * ww.w;
        }
    } else if (gw < B_PAT + N_DIS) {
        isn = true;
        const float4* r = (const float4*)(dn + (size_t)(gw - B_PAT) * DIM);
        const float4* w = (const float4*)(ak + DIM);       // Wn
        #pragma unroll
        for (int k = 0; k < 2; k++) {
            float4 x  = r[lane * 2 + k];
            float4 ww = __ldg(&w[lane * 2 + k]);
            v += x.x * ww.x + x.y * ww.y + x.z * ww.z + x.w * ww.w;
        }
    }
    #pragma unroll
    for (int o = 16; o; o >>= 1) v += __shfl_xor_sync(0xffffffffu, v, o);

    if (lane == 0) {
        if (gw < B_PAT)              g_sp[gw]          = v;
        else if (gw < B_PAT + N_DIS) g_sn[gw - B_PAT]  = v;
    }

    // block-level max over sn rows, one atomic per block
    __shared__ float wmax[8];
    float mv = isn ? v : -CUDART_INF_F;
    if (lane == 0) wmax[tid >> 5] = mv;
    __syncthreads();
    if (tid == 0) {
        float m = wmax[0];
        #pragma unroll
        for (int i = 1; i < 8; i++) m = fmaxf(m, wmax[i]);
        if (m > -CUDART_INF_F) atomicMax(&g_max_enc, enc_f(m));
    }
}

// ---------------- kernel 2: fused softmax-weighted aggregation ----------------
// grid (PT, NS). CTA: 64 patients x 256 dims, over its 625-node split.
// thread tile: 8 patients x 8 dims (dims d = dg*4..+3 and 128+dg*4..+3).
__global__ __launch_bounds__(256) void k_main(const float* __restrict__ dn)
{
    __shared__ float s_v[NK][DIM];     // 32 KB: staged disease-node chunk
    __shared__ float s_w[BM][NK];      // 8 KB: attention weights (unnormalized)
    __shared__ float s_sp[BM];
    __shared__ float s_m[BM];

    const int tid   = threadIdx.x;
    const int ptile = blockIdx.x;
    const int split = blockIdx.y;
    const int b0    = ptile * BM;

    const float max_sn = dec_f(g_max_enc);
    if (tid < BM) {
        float sp = g_sp[b0 + tid];
        s_sp[tid] = sp;
        s_m[tid]  = lrelu(sp + max_sn);   // exact row max of leaky-relu scores
    }
    __syncthreads();

    const int dg = tid & 31;   // dim group: owns d in {dg*4..dg*4+3, 128+dg*4..+3}
    const int bg = tid >> 5;   // patient group (== warp id): patients bg*8..bg*8+7
    const int wb = tid >> 2;   // w-compute: patient 0..63
    const int ws = tid & 3;    // w-compute: n-sub 0..3 (8 n's each)

    const float sp_w = s_sp[wb];
    const float m_w  = s_m[wb];

    float acc[8][8];
    #pragma unroll
    for (int i = 0; i < 8; i++)
        #pragma unroll
        for (int j = 0; j < 8; j++) acc[i][j] = 0.0f;

    float den = 0.0f;
    const int n_begin = split * NPER;
    const int n_end   = n_begin + NPER;
    const float4* src = (const float4*)dn;

    for (int nb = n_begin; nb < n_end; nb += NK) {
        __syncthreads();  // previous accumulate done before overwriting smem

        // stage dn chunk: 2048 float4s, coalesced, zero-pad past n_end
        #pragma unroll
        for (int k = 0; k < 8; k++) {
            int idx = tid + k * 256;
            int nl  = idx >> 6;
            int c   = idx & 63;
            int n   = nb + nl;
            float4 val = (n < n_end) ? src[(size_t)n * 64 + c]
                                     : make_float4(0.f, 0.f, 0.f, 0.f);
            ((float4*)&s_v[nl][0])[c] = val;
        }

        // unnormalized attention weights for this chunk
        #pragma unroll
        for (int j = 0; j < 8; j++) {
            int nl = ws * 8 + j;
            int n  = nb + nl;
            float w = 0.0f;
            if (n < n_end) {
                float s = lrelu(sp_w + __ldg(&g_sn[n]));
                w = __expf(s - m_w);
            }
            s_w[wb][nl] = w;
            den += w;
        }
        __syncthreads();

        // accumulate: 64 FFMA per n per thread, w via smem broadcast
        #pragma unroll
        for (int nl = 0; nl < NK; nl++) {
            float4 v0 = ((const float4*)&s_v[nl][0])[dg];        // d = dg*4
            float4 v1 = ((const float4*)&s_v[nl][0])[dg + 32];   // d = 128+dg*4
            #pragma unroll
            for (int bb = 0; bb < 8; bb++) {
                float w = s_w[bg * 8 + bb][nl];
                acc[bb][0] += w * v0.x;  acc[bb][1] += w * v0.y;
                acc[bb][2] += w * v0.z;  acc[bb][3] += w * v0.w;
                acc[bb][4] += w * v1.x;  acc[bb][5] += w * v1.y;
                acc[bb][6] += w * v1.z;  acc[bb][7] += w * v1.w;
            }
        }
    }

    // denominator: 4 threads per patient -> shfl reduce
    den += __shfl_xor_sync(0xffffffffu, den, 1);
    den += __shfl_xor_sync(0xffffffffu, den, 2);
    if (ws == 0) g_den[split][b0 + wb] = den;

    // write partial numerators (coalesced float4 per warp)
    #pragma unroll
    for (int bb = 0; bb < 8; bb++) {
        int b = b0 + bg * 8 + bb;
        float4* dst = (float4*)&g_num[split][b][0];
        dst[dg]      = make_float4(acc[bb][0], acc[bb][1], acc[bb][2], acc[bb][3]);
        dst[dg + 32] = make_float4(acc[bb][4], acc[bb][5], acc[bb][6], acc[bb][7]);
    }
}

// ---------------- kernel 3: denominator reduce ----------------
__global__ void k_den()
{
    int b = blockIdx.x * blockDim.x + threadIdx.x;
    if (b < B_PAT) {
        float s = 0.0f;
        #pragma unroll
        for (int i = 0; i < NS; i++) s += g_den[i][b];
        g_invden[b] = 1.0f / s;
    }
}

// ---------------- kernel 4: finalize out = pf + num * invden ----------------
__global__ void k_fin(const float* __restrict__ pf, float* __restrict__ out)
{
    int idx = blockIdx.x * blockDim.x + threadIdx.x;   // float4 index
    if (idx >= B_PAT * DIM / 4) return;
    int b = idx >> 6;                                  // 64 float4 per row
    float4 p = ((const float4*)pf)[idx];
    float4 s = make_float4(0.f, 0.f, 0.f, 0.f);
    const float4* num4 = (const float4*)g_num;
    #pragma unroll
    for (int i = 0; i < NS; i++) {
        float4 v = num4[(size_t)i * (B_PAT * DIM / 4) + idx];
        s.x += v.x; s.y += v.y; s.z += v.z; s.w += v.w;
    }
    float inv = g_invden[b];
    float4 o;
    o.x = p.x + s.x * inv;  o.y = p.y + s.y * inv;
    o.z = p.z + s.z * inv;  o.w = p.w + s.w * inv;
    ((float4*)out)[idx] = o;
}

// ---------------- launch ----------------
extern "C" void kernel_launch(void* const* d_in, const int* in_sizes, int n_in,
                              void* d_out, int out_size)
{
    const float* pf = (const float*)d_in[0];   // [4096, 256]
    const float* dn = (const float*)d_in[1];   // [10000, 256]
    const float* ak = (const float*)d_in[2];   // [512, 1]
    float* out = (float*)d_out;

    k_init<<<1, 1>>>();
    k_scores<<<(B_PAT + N_DIS) / 8, 256>>>(pf, dn, ak);
    k_main<<<dim3(PT, NS), 256>>>(dn);
    k_den<<<(B_PAT + 255) / 256, 256>>>();
    k_fin<<<(B_PAT * DIM / 4 + 255) / 256, 256>>>(pf, out);
}

// round 2
// speedup vs baseline: 1.2944x; 1.2944x over previous
#include <cuda_runtime.h>
#include <math_constants.h>

#define B_PAT 4096
#define N_DIS 10000
#define DIM   256
#define BM    64            // patients per CTA tile
#define NK    32            // disease-node chunk staged in smem
#define NS    16            // N splits
#define NPER  (N_DIS / NS)  // 625
#define PT    (B_PAT / BM)  // 64 patient tiles
#define LEAKY 0.2f

typedef unsigned long long ull;

// ---------------- scratch (static device globals; no allocation) ----------------
__device__ float        g_sp[B_PAT];
__device__ float        g_sn[N_DIS];
__device__ unsigned int g_max_enc;
__device__ float        g_num[NS][B_PAT][DIM];   // 67 MB partial numerators
__device__ float        g_den[NS][B_PAT];
__device__ float        g_invden[B_PAT];

// monotonic float<->uint encoding for atomicMax over signed floats
__device__ __forceinline__ unsigned enc_f(float f) {
    unsigned u = __float_as_uint(f);
    return (u & 0x80000000u) ? ~u : (u | 0x80000000u);
}
__device__ __forceinline__ float dec_f(unsigned e) {
    return __uint_as_float((e & 0x80000000u) ? (e ^ 0x80000000u) : ~e);
}
__device__ __forceinline__ float lrelu(float s) {
    return (s >= 0.0f) ? s : LEAKY * s;
}

// ---------------- packed f32x2 helpers ----------------
__device__ __forceinline__ ull pack_dup(float x) {
    ull r;
    asm("mov.b64 %0, {%1, %1};" : "=l"(r) : "f"(x));
    return r;
}
__device__ __forceinline__ void fma2(ull& d, ull a, ull b) {
    asm("fma.rn.f32x2 %0, %1, %2, %0;" : "+l"(d) : "l"(a), "l"(b));
}
__device__ __forceinline__ float2 unpk(ull v) {
    float2 r;
    asm("mov.b64 {%0, %1}, %2;" : "=f"(r.x), "=f"(r.y) : "l"(v));
    return r;
}

// ---------------- kernel 0: reset global max ----------------
__global__ void k_init() { g_max_enc = 0u; }

// ---------------- kernel 1: sp, sn dot products + max(sn) ----------------
__global__ __launch_bounds__(256) void k_scores(
    const float* __restrict__ pf, const float* __restrict__ dn,
    const float* __restrict__ ak)
{
    int tid  = threadIdx.x;
    int lane = tid & 31;
    int gw   = blockIdx.x * 8 + (tid >> 5);

    float v = 0.0f;
    bool isn = false;
    if (gw < B_PAT) {
        const float4* r = (const float4*)(pf + (size_t)gw * DIM);
        const float4* w = (const float4*)ak;               // Wp
        #pragma unroll
        for (int k = 0; k < 2; k++) {
            float4 x  = r[lane * 2 + k];
            float4 ww = __ldg(&w[lane * 2 + k]);
            v += x.x * ww.x + x.y * ww.y + x.z * ww.z + x.w * ww.w;
        }
    } else if (gw < B_PAT + N_DIS) {
        isn = true;
        const float4* r = (const float4*)(dn + (size_t)(gw - B_PAT) * DIM);
        const float4* w = (const float4*)(ak + DIM);       // Wn
        #pragma unroll
        for (int k = 0; k < 2; k++) {
            float4 x  = r[lane * 2 + k];
            float4 ww = __ldg(&w[lane * 2 + k]);
            v += x.x * ww.x + x.y * ww.y + x.z * ww.z + x.w * ww.w;
        }
    }
    #pragma unroll
    for (int o = 16; o; o >>= 1) v += __shfl_xor_sync(0xffffffffu, v, o);

    if (lane == 0) {
        if (gw < B_PAT)              g_sp[gw]          = v;
        else if (gw < B_PAT + N_DIS) g_sn[gw - B_PAT]  = v;
    }

    __shared__ float wmax[8];
    float mv = isn ? v : -CUDART_INF_F;
    if (lane == 0) wmax[tid >> 5] = mv;
    __syncthreads();
    if (tid == 0) {
        float m = wmax[0];
        #pragma unroll
        for (int i = 1; i < 8; i++) m = fmaxf(m, wmax[i]);
        if (m > -CUDART_INF_F) atomicMax(&g_max_enc, enc_f(m));
    }
}

// ---------------- kernel 2: fused softmax-weighted aggregation ----------------
// grid (PT, NS). CTA: 64 patients x 256 dims over its 625-node split.
// Thread tile: 8 patients x 8 dims, patients processed as 4 f32x2 PAIRS.
// Inner op: fma.rn.f32x2 (packed dual FMA) -> 2x fp32 throughput vs FFMA.
__global__ __launch_bounds__(256, 2) void k_main(const float* __restrict__ dn)
{
    __shared__ float s_v[NK][DIM];     // 32 KB: staged disease-node chunk
    __shared__ float s_w[NK][BM];      // 8 KB: weights, PATIENT-contiguous rows
    __shared__ float s_sp[BM];
    __shared__ float s_m[BM];

    const int tid   = threadIdx.x;
    const int ptile = blockIdx.x;
    const int split = blockIdx.y;
    const int b0    = ptile * BM;

    const float max_sn = dec_f(g_max_enc);
    if (tid < BM) {
        float sp = g_sp[b0 + tid];
        s_sp[tid] = sp;
        s_m[tid]  = lrelu(sp + max_sn);   // exact row max of leaky-relu scores
    }
    __syncthreads();

    const int dg = tid & 31;   // dim group: d in {dg*4..+3, 128+dg*4..+3}
    const int bg = tid >> 5;   // patient group (warp id): patients bg*8..+7
    const int wb = tid >> 2;   // w-compute: patient 0..63
    const int ws = tid & 3;    // w-compute: n-sub 0..3 (8 n's each)

    const float sp_w = s_sp[wb];
    const float m_w  = s_m[wb];

    // acc2[p][j]: packed pair (patient bg*8+2p, bg*8+2p+1), dim index j
    ull acc2[4][8];
    #pragma unroll
    for (int p = 0; p < 4; p++)
        #pragma unroll
        for (int j = 0; j < 8; j++) acc2[p][j] = 0ULL;

    float den = 0.0f;
    const int n_begin = split * NPER;
    const int n_end   = n_begin + NPER;
    const float4* src = (const float4*)dn;

    for (int nb = n_begin; nb < n_end; nb += NK) {
        __syncthreads();

        // stage dn chunk: 2048 float4s, coalesced, zero-pad past n_end
        #pragma unroll
        for (int k = 0; k < 8; k++) {
            int idx = tid + k * 256;
            int nl  = idx >> 6;
            int c   = idx & 63;
            int n   = nb + nl;
            float4 val = (n < n_end) ? src[(size_t)n * 64 + c]
                                     : make_float4(0.f, 0.f, 0.f, 0.f);
            ((float4*)&s_v[nl][0])[c] = val;
        }

        // unnormalized attention weights, stored [nl][patient]
        #pragma unroll
        for (int j = 0; j < 8; j++) {
            int nl = ws * 8 + j;
            int n  = nb + nl;
            float w = 0.0f;
            if (n < n_end) {
                float s = lrelu(sp_w + __ldg(&g_sn[n]));
                w = __expf(s - m_w);
            }
            s_w[nl][wb] = w;
            den += w;
        }
        __syncthreads();

        // accumulate: 32 packed f32x2 FMAs per n per thread
        #pragma unroll
        for (int nl = 0; nl < NK; nl++) {
            const float* vrow = &s_v[nl][0];
            float4 v0 = ((const float4*)vrow)[dg];        // d = dg*4
            float4 v1 = ((const float4*)vrow)[dg + 32];   // d = 128+dg*4
            ull vd[8];
            vd[0] = pack_dup(v0.x); vd[1] = pack_dup(v0.y);
            vd[2] = pack_dup(v0.z); vd[3] = pack_dup(v0.w);
            vd[4] = pack_dup(v1.x); vd[5] = pack_dup(v1.y);
            vd[6] = pack_dup(v1.z); vd[7] = pack_dup(v1.w);

            // packed weight pairs: (w[2p], w[2p+1]) via one LDS.64 each (broadcast)
            const ull* wp = (const ull*)&s_w[nl][bg * 8];
            ull w2[4];
            w2[0] = wp[0]; w2[1] = wp[1]; w2[2] = wp[2]; w2[3] = wp[3];

            #pragma unroll
            for (int p = 0; p < 4; p++)
                #pragma unroll
                for (int j = 0; j < 8; j++)
                    fma2(acc2[p][j], w2[p], vd[j]);
        }
    }

    // denominator: 4 threads per patient -> shfl reduce
    den += __shfl_xor_sync(0xffffffffu, den, 1);
    den += __shfl_xor_sync(0xffffffffu, den, 2);
    if (ws == 0) g_den[split][b0 + wb] = den;

    // unpack pairs and write partial numerators (coalesced float4 per warp)
    #pragma unroll
    for (int p = 0; p < 4; p++) {
        float a0[8], a1[8];
        #pragma unroll
        for (int j = 0; j < 8; j++) {
            float2 f = unpk(acc2[p][j]);
            a0[j] = f.x; a1[j] = f.y;
        }
        int b = b0 + bg * 8 + p * 2;
        float4* dst0 = (float4*)&g_num[split][b][0];
        float4* dst1 = (float4*)&g_num[split][b + 1][0];
        dst0[dg]      = make_float4(a0[0], a0[1], a0[2], a0[3]);
        dst0[dg + 32] = make_float4(a0[4], a0[5], a0[6], a0[7]);
        dst1[dg]      = make_float4(a1[0], a1[1], a1[2], a1[3]);
        dst1[dg + 32] = make_float4(a1[4], a1[5], a1[6], a1[7]);
    }
}

// ---------------- kernel 3: denominator reduce ----------------
__global__ void k_den()
{
    int b = blockIdx.x * blockDim.x + threadIdx.x;
    if (b < B_PAT) {
        float s = 0.0f;
        #pragma unroll
        for (int i = 0; i < NS; i++) s += g_den[i][b];
        g_invden[b] = 1.0f / s;
    }
}

// ---------------- kernel 4: finalize out = pf + num * invden ----------------
__global__ void k_fin(const float* __restrict__ pf, float* __restrict__ out)
{
    int idx = blockIdx.x * blockDim.x + threadIdx.x;   // float4 index
    if (idx >= B_PAT * DIM / 4) return;
    int b = idx >> 6;                                  // 64 float4 per row
    float4 p = ((const float4*)pf)[idx];
    float4 s = make_float4(0.f, 0.f, 0.f, 0.f);
    const float4* num4 = (const float4*)g_num;
    #pragma unroll
    for (int i = 0; i < NS; i++) {
        float4 v = num4[(size_t)i * (B_PAT * DIM / 4) + idx];
        s.x += v.x; s.y += v.y; s.z += v.z; s.w += v.w;
    }
    float inv = g_invden[b];
    float4 o;
    o.x = p.x + s.x * inv;  o.y = p.y + s.y * inv;
    o.z = p.z + s.z * inv;  o.w = p.w + s.w * inv;
    ((float4*)out)[idx] = o;
}

// ---------------- launch ----------------
extern "C" void kernel_launch(void* const* d_in, const int* in_sizes, int n_in,
                              void* d_out, int out_size)
{
    const float* pf = (const float*)d_in[0];   // [4096, 256]
    const float* dn = (const float*)d_in[1];   // [10000, 256]
    const float* ak = (const float*)d_in[2];   // [512, 1]
    float* out = (float*)d_out;

    k_init<<<1, 1>>>();
    k_scores<<<(B_PAT + N_DIS) / 8, 256>>>(pf, dn, ak);
    k_main<<<dim3(PT, NS), 256>>>(dn);
    k_den<<<(B_PAT + 255) / 256, 256>>>();
    k_fin<<<(B_PAT * DIM / 4 + 255) / 256, 256>>>(pf, out);
}

// round 5
// speedup vs baseline: 3.7292x; 2.8810x over previous
#include <cuda_runtime.h>
#include <cuda_bf16.h>
#include <math_constants.h>
#include <cstdint>

#define B_PAT 4096
#define N_DIS 10000
#define DIM   256
#define BM    128                 // patients per CTA (GEMM M)
#define KC    64                  // nodes per chunk (GEMM K chunk)
#define NSK   4                   // K splits
#define NPER  (N_DIS/NSK)         // 2500 valid nodes per split
#define NCH   ((NPER+KC-1)/KC)    // 40 chunks per split
#define NPADS (NCH*KC)            // 2560 padded columns per split
#define NPAD  (NSK*NPADS)         // 10240
#define PT    (B_PAT/BM)          // 32
#define LEAKY 0.2f
#define L2EF  1.4426950408889634f

// dynamic smem layout
#define A_BYTES  (BM*KC*2)                // 16384 per buffer
#define B_BYTES  (DIM*KC*2)               // 32768 per buffer
#define OFF_A    0
#define OFF_B    (2*A_BYTES)              // 32768
#define OFF_SN   (OFF_B + 2*B_BYTES)      // 98304
#define OFF_DEN  (OFF_SN + NPER*4)        // 108304
#define SMEM_TOTAL (OFF_DEN + BM*4)       // 108816

typedef uint32_t u32;

// ---------------- device globals (no allocation) ----------------
__device__ float        g_sp[B_PAT];
__device__ float        g_sn[N_DIS];
__device__ unsigned int g_max_enc;
// padded split-major transpose: split s owns padded cols [s*NPADS, (s+1)*NPADS);
// padded col p = s*NPADS + i maps to node s*NPER + i for i < NPER, else zero.
__device__ __align__(16) __nv_bfloat16 g_dnT[DIM][NPAD];
__device__ float        g_num[NSK][B_PAT][DIM];  // partial numerators
__device__ float        g_den[NSK][B_PAT];
__device__ float        g_invden[B_PAT];

// ---------------- helpers ----------------
__device__ __forceinline__ unsigned enc_f(float f) {
    unsigned u = __float_as_uint(f);
    return (u & 0x80000000u) ? ~u : (u | 0x80000000u);
}
__device__ __forceinline__ float dec_f(unsigned e) {
    return __uint_as_float((e & 0x80000000u) ? (e ^ 0x80000000u) : ~e);
}
__device__ __forceinline__ float ex2(float x) {
    float r; asm("ex2.approx.ftz.f32 %0, %1;" : "=f"(r) : "f"(x)); return r;
}
__device__ __forceinline__ u32 smem_u32(const void* p) {
    u32 a;
    asm("{ .reg .u64 t; cvta.to.shared.u64 t, %1; cvt.u32.u64 %0, t; }" : "=r"(a) : "l"(p));
    return a;
}
// XOR-swizzled byte offset within a [rows x 64] bf16 tile (128B rows).
__device__ __forceinline__ u32 swoff(int r, int k) {
    return (u32)(r * 128 + ((((k >> 3) ^ (r & 7))) << 4) + (k & 7) * 2);
}
__device__ __forceinline__ void mma16816(float* c, const u32* a, u32 b0, u32 b1) {
    asm volatile(
        "mma.sync.aligned.m16n8k16.row.col.f32.bf16.bf16.f32 "
        "{%0,%1,%2,%3}, {%4,%5,%6,%7}, {%8,%9}, {%0,%1,%2,%3};"
        : "+f"(c[0]), "+f"(c[1]), "+f"(c[2]), "+f"(c[3])
        : "r"(a[0]), "r"(a[1]), "r"(a[2]), "r"(a[3]), "r"(b0), "r"(b1));
}
__device__ __forceinline__ void cp_async16(u32 dst, const void* src) {
    asm volatile("cp.async.ca.shared.global [%0], [%1], 16;" :: "r"(dst), "l"(src) : "memory");
}

// ---------------- kernel 0: reset global max ----------------
__global__ void k_init() { g_max_enc = 0u; }

// ---------------- kernel 1: transpose + bf16 convert dn -> g_dnT (padded) ----------------
__global__ __launch_bounds__(256) void k_cvt(const float* __restrict__ dn)
{
    __shared__ __nv_bfloat16 s[64][72];
    int p0 = blockIdx.x * 64, d0 = blockIdx.y * 64;   // padded cols, dims
    int tid = threadIdx.x;
    #pragma unroll
    for (int i = 0; i < 16; i++) {
        int idx = tid + i * 256;
        int pl = idx >> 6, dl = idx & 63;
        int p  = p0 + pl;
        int sp_ = p / NPADS, ii = p % NPADS;
        float v = 0.0f;
        if (ii < NPER) {
            int node = sp_ * NPER + ii;
            v = dn[(size_t)node * DIM + d0 + dl];
        }
        s[pl][dl] = __float2bfloat16(v);
    }
    __syncthreads();
    #pragma unroll
    for (int i = 0; i < 16; i++) {
        int idx = tid + i * 256;
        int dl = idx >> 6, pl = idx & 63;
        g_dnT[d0 + dl][p0 + pl] = s[pl][dl];
    }
}

// ---------------- kernel 2: sp, sn dot products + max(sn) ----------------
__global__ __launch_bounds__(256) void k_scores(
    const float* __restrict__ pf, const float* __restrict__ dn,
    const float* __restrict__ ak)
{
    int tid  = threadIdx.x;
    int lane = tid & 31;
    int gw   = blockIdx.x * 8 + (tid >> 5);

    float v = 0.0f;
    bool isn = false;
    if (gw < B_PAT) {
        const float4* r = (const float4*)(pf + (size_t)gw * DIM);
        const float4* w = (const float4*)ak;
        #pragma unroll
        for (int k = 0; k < 2; k++) {
            float4 x  = r[lane * 2 + k];
            float4 ww = __ldg(&w[lane * 2 + k]);
            v += x.x * ww.x + x.y * ww.y + x.z * ww.z + x.w * ww.w;
        }
    } else if (gw < B_PAT + N_DIS) {
        isn = true;
        const float4* r = (const float4*)(dn + (size_t)(gw - B_PAT) * DIM);
        const float4* w = (const float4*)(ak + DIM);
        #pragma unroll
        for (int k = 0; k < 2; k++) {
            float4 x  = r[lane * 2 + k];
            float4 ww = __ldg(&w[lane * 2 + k]);
            v += x.x * ww.x + x.y * ww.y + x.z * ww.z + x.w * ww.w;
        }
    }
    #pragma unroll
    for (int o = 16; o; o >>= 1) v += __shfl_xor_sync(0xffffffffu, v, o);

    if (lane == 0) {
        if (gw < B_PAT)              g_sp[gw]         = v;
        else if (gw < B_PAT + N_DIS) g_sn[gw - B_PAT] = v;
    }

    __shared__ float wmax[8];
    float mv = isn ? v : -CUDART_INF_F;
    if (lane == 0) wmax[tid >> 5] = mv;
    __syncthreads();
    if (tid == 0) {
        float m = wmax[0];
        #pragma unroll
        for (int i = 1; i < 8; i++) m = fmaxf(m, wmax[i]);
        if (m > -CUDART_INF_F) atomicMax(&g_max_enc, enc_f(m));
    }
}

// ---------------- kernel 3: main fused GEMM via mma.sync bf16 ----------------
// grid (PT, NSK), 256 threads = 8 warps, warp tile 64x64 (2M x 4N grid).
__global__ __launch_bounds__(256, 1) void k_main()
{
    extern __shared__ char smem[];
    char*  As_base = smem + OFF_A;
    char*  Bs_base = smem + OFF_B;
    float* sn_s    = (float*)(smem + OFF_SN);
    float* den_s   = (float*)(smem + OFF_DEN);
    const u32 sbB  = smem_u32(Bs_base);

    const int tid  = threadIdx.x;
    const int wid  = tid >> 5;
    const int lane = tid & 31;
    const int wm   = wid & 1;        // warp m: 0..1 (64 rows each)
    const int wn   = wid >> 1;       // warp n: 0..3 (64 dims each)
    const int g    = lane >> 2;      // fragment group row 0..7
    const int tig  = lane & 3;       // thread-in-group 0..3
    const int split = blockIdx.y;
    const int b0p   = blockIdx.x * BM;
    const int nbase = split * NPER;       // valid-node base (for sn)
    const int pbase = split * NPADS;      // padded-column base (for g_dnT)

    const int arow  = tid & 127;
    const int khalf = tid >> 7;

    const float sp    = g_sp[b0p + arow];
    const float maxsn = dec_f(g_max_enc);
    float mt = sp + maxsn;
    mt = fmaxf(mt, LEAKY * mt);                 // exact row max of scores
    const float mL2E = mt * L2EF;
    float den = 0.0f;

    for (int i = tid; i < NPER; i += 256) sn_s[i] = g_sn[nbase + i];

    auto fill_A = [&](int c) {
        char* ab = As_base + (c & 1) * A_BYTES;
        #pragma unroll
        for (int gq = 0; gq < 4; gq++) {
            u32 pk[4];
            #pragma unroll
            for (int e = 0; e < 4; e++) {
                int kl   = khalf * 32 + gq * 8 + e * 2;
                int kloc = c * KC + kl;
                float sn0 = (kloc     < NPER) ? sn_s[kloc]     : -CUDART_INF_F;
                float sn1 = (kloc + 1 < NPER) ? sn_s[kloc + 1] : -CUDART_INF_F;
                float t0 = sp + sn0, t1 = sp + sn1;
                t0 = fmaxf(t0, LEAKY * t0);
                t1 = fmaxf(t1, LEAKY * t1);
                float w0 = ex2(fmaf(t0, L2EF, -mL2E));
                float w1 = ex2(fmaf(t1, L2EF, -mL2E));
                den += w0 + w1;
                asm("cvt.rn.satfinite.bf16x2.f32 %0, %1, %2;" : "=r"(pk[e]) : "f"(w1), "f"(w0));
            }
            int k8 = khalf * 4 + gq;
            *(uint4*)(ab + arow * 128 + ((k8 ^ (arow & 7)) << 4)) =
                make_uint4(pk[0], pk[1], pk[2], pk[3]);
        }
    };
    auto fill_B = [&](int c) {                  // cp.async, 8 x 16B per thread
        u32 bb = sbB + (u32)((c & 1) * B_BYTES);
        int p0c = pbase + c * KC;               // 64-aligned padded column -> 16B-aligned src
        #pragma unroll
        for (int it = 0; it < 8; it++) {
            int u  = tid + it * 256;            // 0..2047
            int d  = u >> 3;                    // dim row 0..255
            int k8 = u & 7;
            const void* src = (const char*)g_dnT + (size_t)d * (NPAD * 2)
                            + (size_t)(p0c + k8 * 8) * 2;
            cp_async16(bb + (u32)(d * 128 + ((k8 ^ (d & 7)) << 4)), src);
        }
        asm volatile("cp.async.commit_group;" ::: "memory");
    };

    float acc[4][8][4];
    #pragma unroll
    for (int i = 0; i < 4; i++)
        #pragma unroll
        for (int j = 0; j < 8; j++)
            #pragma unroll
            for (int q = 0; q < 4; q++) acc[i][j][q] = 0.0f;

    fill_B(0);
    __syncthreads();      // sn_s ready before fill_A reads it
    fill_A(0);
    asm volatile("cp.async.wait_group 0;" ::: "memory");
    __syncthreads();

    for (int c = 0; c < NCH; c++) {
        if (c + 1 < NCH) { fill_B(c + 1); fill_A(c + 1); }

        const char* As = As_base + (c & 1) * A_BYTES;
        const char* Bs = Bs_base + (c & 1) * B_BYTES;
        #pragma unroll
        for (int ks = 0; ks < 4; ks++) {
            const int kk = ks * 16 + tig * 2;
            u32 a[4][4];
            #pragma unroll
            for (int i = 0; i < 4; i++) {
                int r = wm * 64 + i * 16 + g;
                a[i][0] = *(const u32*)(As + swoff(r,     kk));
                a[i][1] = *(const u32*)(As + swoff(r + 8, kk));
                a[i][2] = *(const u32*)(As + swoff(r,     kk + 8));
                a[i][3] = *(const u32*)(As + swoff(r + 8, kk + 8));
            }
            #pragma unroll
            for (int j = 0; j < 8; j++) {
                int d  = wn * 64 + j * 8 + g;
                u32 b0 = *(const u32*)(Bs + swoff(d, kk));
                u32 b1 = *(const u32*)(Bs + swoff(d, kk + 8));
                #pragma unroll
                for (int i = 0; i < 4; i++) mma16816(acc[i][j], a[i], b0, b1);
            }
        }
        if (c + 1 < NCH) asm volatile("cp.async.wait_group 0;" ::: "memory");
        __syncthreads();
    }

    // denominator reduce (fp32 exact)
    if (khalf == 0) den_s[arow] = den;
    __syncthreads();
    if (khalf == 1) den_s[arow] += den;
    __syncthreads();
    if (khalf == 0) g_den[split][b0p + arow] = den_s[arow];

    // epilogue: accumulators -> g_num
    #pragma unroll
    for (int i = 0; i < 4; i++) {
        int m = b0p + wm * 64 + i * 16 + g;
        #pragma unroll
        for (int j = 0; j < 8; j++) {
            int col = wn * 64 + j * 8 + tig * 2;
            *(float2*)&g_num[split][m][col]     = make_float2(acc[i][j][0], acc[i][j][1]);
            *(float2*)&g_num[split][m + 8][col] = make_float2(acc[i][j][2], acc[i][j][3]);
        }
    }
}

// ---------------- kernel 4: denominator reduce ----------------
__global__ void k_den()
{
    int b = blockIdx.x * blockDim.x + threadIdx.x;
    if (b < B_PAT) {
        float s = 0.0f;
        #pragma unroll
        for (int i = 0; i < NSK; i++) s += g_den[i][b];
        g_invden[b] = 1.0f / s;
    }
}

// ---------------- kernel 5: finalize out = pf + num * invden ----------------
__global__ void k_fin(const float* __restrict__ pf, float* __restrict__ out)
{
    int idx = blockIdx.x * blockDim.x + threadIdx.x;   // float4 index
    if (idx >= B_PAT * DIM / 4) return;
    int b = idx >> 6;
    float4 p = ((const float4*)pf)[idx];
    float4 s = make_float4(0.f, 0.f, 0.f, 0.f);
    const float4* num4 = (const float4*)g_num;
    #pragma unroll
    for (int i = 0; i < NSK; i++) {
        float4 v = num4[(size_t)i * (B_PAT * DIM / 4) + idx];
        s.x += v.x; s.y += v.y; s.z += v.z; s.w += v.w;
    }
    float inv = g_invden[b];
    float4 o;
    o.x = p.x + s.x * inv;  o.y = p.y + s.y * inv;
    o.z = p.z + s.z * inv;  o.w = p.w + s.w * inv;
    ((float4*)out)[idx] = o;
}

// ---------------- launch ----------------
extern "C" void kernel_launch(void* const* d_in, const int* in_sizes, int n_in,
                              void* d_out, int out_size)
{
    const float* pf = (const float*)d_in[0];
    const float* dn = (const float*)d_in[1];
    const float* ak = (const float*)d_in[2];
    float* out = (float*)d_out;

    static int configured = 0;
    if (!configured) {
        cudaFuncSetAttribute(k_main, cudaFuncAttributeMaxDynamicSharedMemorySize, SMEM_TOTAL);
        configured = 1;
    }

    k_init<<<1, 1>>>();
    k_cvt<<<dim3(NPAD / 64, DIM / 64), 256>>>(dn);
    k_scores<<<(B_PAT + N_DIS) / 8, 256>>>(pf, dn, ak);
    k_main<<<dim3(PT, NSK), 256, SMEM_TOTAL>>>();
    k_den<<<(B_PAT + 255) / 256, 256>>>();
    k_fin<<<(B_PAT * DIM / 4 + 255) / 256, 256>>>(pf, out);
}

// round 6
// speedup vs baseline: 6.1003x; 1.6358x over previous
#include <cuda_runtime.h>
#include <cuda_bf16.h>
#include <math_constants.h>
#include <cstdint>

#define B_PAT 4096
#define N_DIS 10000
#define DIM   256
#define BM    128                 // patients per CTA (GEMM M)
#define KC    64                  // nodes per chunk (GEMM K chunk)
#define NSK   4                   // K splits
#define NPER  (N_DIS/NSK)         // 2500 valid nodes per split
#define NCH   ((NPER+KC-1)/KC)    // 40 chunks per split
#define NPADS (NCH*KC)            // 2560 padded columns per split
#define NPAD  (NSK*NPADS)         // 10240
#define PT    (B_PAT/BM)          // 32
#define NTHR  512                 // 16 warps
#define LEAKY 0.2f
#define L2EF  1.4426950408889634f

// dynamic smem layout
#define A_BYTES  (BM*KC*2)                // 16384 per buffer
#define B_BYTES  (DIM*KC*2)               // 32768 per buffer
#define OFF_A    0
#define OFF_B    (2*A_BYTES)              // 32768
#define OFF_SN   (OFF_B + 2*B_BYTES)      // 98304
#define OFF_DEN  (OFF_SN + NPER*4)        // 108304
#define SMEM_TOTAL (OFF_DEN + NTHR*4)     // 110352

typedef uint32_t u32;

// ---------------- device globals (no allocation) ----------------
__device__ float        g_sp[B_PAT];
__device__ float        g_sn[N_DIS];
__device__ unsigned int g_max_enc;
// padded split-major transpose: split s owns padded cols [s*NPADS, (s+1)*NPADS)
__device__ __align__(16) __nv_bfloat16 g_dnT[DIM][NPAD];
__device__ float        g_num[NSK][B_PAT][DIM];
__device__ float        g_den[NSK][B_PAT];
__device__ float        g_invden[B_PAT];

// ---------------- helpers ----------------
__device__ __forceinline__ unsigned enc_f(float f) {
    unsigned u = __float_as_uint(f);
    return (u & 0x80000000u) ? ~u : (u | 0x80000000u);
}
__device__ __forceinline__ float dec_f(unsigned e) {
    return __uint_as_float((e & 0x80000000u) ? (e ^ 0x80000000u) : ~e);
}
__device__ __forceinline__ float ex2(float x) {
    float r; asm("ex2.approx.ftz.f32 %0, %1;" : "=f"(r) : "f"(x)); return r;
}
__device__ __forceinline__ u32 smem_u32(const void* p) {
    u32 a;
    asm("{ .reg .u64 t; cvta.to.shared.u64 t, %1; cvt.u32.u64 %0, t; }" : "=r"(a) : "l"(p));
    return a;
}
// XOR-swizzled byte offset within a [rows x 64] bf16 tile (128B rows).
__device__ __forceinline__ u32 swoff(int r, int k) {
    return (u32)(r * 128 + ((((k >> 3) ^ (r & 7))) << 4) + (k & 7) * 2);
}
__device__ __forceinline__ void mma16816(float* c, const u32* a, u32 b0, u32 b1) {
    asm volatile(
        "mma.sync.aligned.m16n8k16.row.col.f32.bf16.bf16.f32 "
        "{%0,%1,%2,%3}, {%4,%5,%6,%7}, {%8,%9}, {%0,%1,%2,%3};"
        : "+f"(c[0]), "+f"(c[1]), "+f"(c[2]), "+f"(c[3])
        : "r"(a[0]), "r"(a[1]), "r"(a[2]), "r"(a[3]), "r"(b0), "r"(b1));
}
__device__ __forceinline__ void ldsm4(u32 addr, u32* r) {
    asm volatile("ldmatrix.sync.aligned.m8n8.x4.shared.b16 {%0,%1,%2,%3}, [%4];"
        : "=r"(r[0]), "=r"(r[1]), "=r"(r[2]), "=r"(r[3]) : "r"(addr));
}
__device__ __forceinline__ void cp_async16(u32 dst, const void* src) {
    asm volatile("cp.async.ca.shared.global [%0], [%1], 16;" :: "r"(dst), "l"(src) : "memory");
}

// ---------------- kernel 0: reset global max ----------------
__global__ void k_init() { g_max_enc = 0u; }

// ---------------- kernel 1: transpose + bf16 convert dn -> g_dnT (padded) ----------------
__global__ __launch_bounds__(256) void k_cvt(const float* __restrict__ dn)
{
    __shared__ __nv_bfloat16 s[64][72];
    int p0 = blockIdx.x * 64, d0 = blockIdx.y * 64;
    int tid = threadIdx.x;
    #pragma unroll
    for (int i = 0; i < 16; i++) {
        int idx = tid + i * 256;
        int pl = idx >> 6, dl = idx & 63;
        int p  = p0 + pl;
        int sp_ = p / NPADS, ii = p % NPADS;
        float v = 0.0f;
        if (ii < NPER) {
            int node = sp_ * NPER + ii;
            v = dn[(size_t)node * DIM + d0 + dl];
        }
        s[pl][dl] = __float2bfloat16(v);
    }
    __syncthreads();
    #pragma unroll
    for (int i = 0; i < 16; i++) {
        int idx = tid + i * 256;
        int dl = idx >> 6, pl = idx & 63;
        g_dnT[d0 + dl][p0 + pl] = s[pl][dl];
    }
}

// ---------------- kernel 2: sp, sn dot products + max(sn) ----------------
__global__ __launch_bounds__(256) void k_scores(
    const float* __restrict__ pf, const float* __restrict__ dn,
    const float* __restrict__ ak)
{
    int tid  = threadIdx.x;
    int lane = tid & 31;
    int gw   = blockIdx.x * 8 + (tid >> 5);

    float v = 0.0f;
    bool isn = false;
    if (gw < B_PAT) {
        const float4* r = (const float4*)(pf + (size_t)gw * DIM);
        const float4* w = (const float4*)ak;
        #pragma unroll
        for (int k = 0; k < 2; k++) {
            float4 x  = r[lane * 2 + k];
            float4 ww = __ldg(&w[lane * 2 + k]);
            v += x.x * ww.x + x.y * ww.y + x.z * ww.z + x.w * ww.w;
        }
    } else if (gw < B_PAT + N_DIS) {
        isn = true;
        const float4* r = (const float4*)(dn + (size_t)(gw - B_PAT) * DIM);
        const float4* w = (const float4*)(ak + DIM);
        #pragma unroll
        for (int k = 0; k < 2; k++) {
            float4 x  = r[lane * 2 + k];
            float4 ww = __ldg(&w[lane * 2 + k]);
            v += x.x * ww.x + x.y * ww.y + x.z * ww.z + x.w * ww.w;
        }
    }
    #pragma unroll
    for (int o = 16; o; o >>= 1) v += __shfl_xor_sync(0xffffffffu, v, o);

    if (lane == 0) {
        if (gw < B_PAT)              g_sp[gw]         = v;
        else if (gw < B_PAT + N_DIS) g_sn[gw - B_PAT] = v;
    }

    __shared__ float wmax[8];
    float mv = isn ? v : -CUDART_INF_F;
    if (lane == 0) wmax[tid >> 5] = mv;
    __syncthreads();
    if (tid == 0) {
        float m = wmax[0];
        #pragma unroll
        for (int i = 1; i < 8; i++) m = fmaxf(m, wmax[i]);
        if (m > -CUDART_INF_F) atomicMax(&g_max_enc, enc_f(m));
    }
}

// ---------------- kernel 3: main fused GEMM, 16 warps, ldmatrix + mma ----------------
// grid (PT, NSK), 512 threads. Warp tile 32x64: wm=wid&3 (32 rows), wn=wid>>2 (64 dims).
__global__ __launch_bounds__(NTHR, 1) void k_main()
{
    extern __shared__ char smem[];
    char*  As_base = smem + OFF_A;
    float* sn_s    = (float*)(smem + OFF_SN);
    float* den_s   = (float*)(smem + OFF_DEN);
    const u32 sbA  = smem_u32(As_base);
    const u32 sbB  = sbA + OFF_B;

    const int tid  = threadIdx.x;
    const int wid  = tid >> 5;
    const int lane = tid & 31;
    const int wm   = wid & 3;        // 4 warp-rows of 32 patients
    const int wn   = wid >> 2;       // 4 warp-cols of 64 dims
    const int g    = lane >> 2;
    const int tig  = lane & 3;
    const int split = blockIdx.y;
    const int b0p   = blockIdx.x * BM;
    const int nbase = split * NPER;
    const int pbase = split * NPADS;

    const int arow = tid & 127;      // A-fill: patient row
    const int kq   = tid >> 7;       // A-fill: k-quarter 0..3 (16 k's each)

    const float sp    = g_sp[b0p + arow];
    const float maxsn = dec_f(g_max_enc);
    float mt = sp + maxsn;
    mt = fmaxf(mt, LEAKY * mt);
    const float mL2E = mt * L2EF;
    float den = 0.0f;

    for (int i = tid; i < NPER; i += NTHR) sn_s[i] = g_sn[nbase + i];

    auto fill_A = [&](int c) {
        char* ab = As_base + (c & 1) * A_BYTES;
        #pragma unroll
        for (int gq = 0; gq < 2; gq++) {
            u32 pk[4];
            #pragma unroll
            for (int e = 0; e < 4; e++) {
                int kl   = kq * 16 + gq * 8 + e * 2;
                int kloc = c * KC + kl;
                float sn0 = (kloc     < NPER) ? sn_s[kloc]     : -CUDART_INF_F;
                float sn1 = (kloc + 1 < NPER) ? sn_s[kloc + 1] : -CUDART_INF_F;
                float t0 = sp + sn0, t1 = sp + sn1;
                t0 = fmaxf(t0, LEAKY * t0);
                t1 = fmaxf(t1, LEAKY * t1);
                float w0 = ex2(fmaf(t0, L2EF, -mL2E));
                float w1 = ex2(fmaf(t1, L2EF, -mL2E));
                den += w0 + w1;
                asm("cvt.rn.satfinite.bf16x2.f32 %0, %1, %2;" : "=r"(pk[e]) : "f"(w1), "f"(w0));
            }
            int k8 = kq * 2 + gq;
            *(uint4*)(ab + arow * 128 + ((k8 ^ (arow & 7)) << 4)) =
                make_uint4(pk[0], pk[1], pk[2], pk[3]);
        }
    };
    auto fill_B = [&](int c) {                  // cp.async, 4 x 16B per thread
        u32 bb = sbB + (u32)((c & 1) * B_BYTES);
        int p0c = pbase + c * KC;
        #pragma unroll
        for (int it = 0; it < 4; it++) {
            int u  = tid + it * NTHR;           // 0..2047
            int d  = u >> 3;
            int k8 = u & 7;
            const void* src = (const char*)g_dnT + (size_t)d * (NPAD * 2)
                            + (size_t)(p0c + k8 * 8) * 2;
            cp_async16(bb + (u32)(d * 128 + ((k8 ^ (d & 7)) << 4)), src);
        }
        asm volatile("cp.async.commit_group;" ::: "memory");
    };

    // ldmatrix address row components (constant across chunks)
    const int a_r  = wm * 32 + (lane & 15);            // + i*16 ; khalf = lane>>4
    const int a_kh = lane >> 4;
    const int b_r  = wn * 64 + (lane >> 4) * 8 + (lane & 7);  // wait: jsel
    // B mapping: matrices m0..m3 = (j0,kh0),(j0,kh1),(j1,kh0),(j1,kh1)
    //   threads 0-7 -> m0, 8-15 -> m1, 16-23 -> m2, 24-31 -> m3
    const int b_jsel = lane >> 4;          // 0..1  (j within pair)
    const int b_kh   = (lane >> 3) & 1;    // 0..1  (k half)
    const int b_row  = (lane & 7);         // row within 8x8

    float acc[2][8][4];
    #pragma unroll
    for (int i = 0; i < 2; i++)
        #pragma unroll
        for (int j = 0; j < 8; j++)
            #pragma unroll
            for (int q = 0; q < 4; q++) acc[i][j][q] = 0.0f;

    fill_B(0);
    __syncthreads();      // sn_s ready before fill_A
    fill_A(0);
    asm volatile("cp.async.wait_group 0;" ::: "memory");
    __syncthreads();

    for (int c = 0; c < NCH; c++) {
        if (c + 1 < NCH) { fill_B(c + 1); fill_A(c + 1); }

        const u32 Aoff = sbA + (u32)((c & 1) * A_BYTES);
        const u32 Boff = sbB + (u32)((c & 1) * B_BYTES);
        #pragma unroll
        for (int ks = 0; ks < 4; ks++) {
            // A fragments: 2 i-tiles, one ldmatrix.x4 each
            u32 a[2][4];
            #pragma unroll
            for (int i = 0; i < 2; i++) {
                int r = a_r + i * 16;
                int k = ks * 16 + a_kh * 8;
                ldsm4(Aoff + (u32)(r * 128 + ((((k >> 3) ^ (r & 7))) << 4)), a[i]);
            }
            // B fragments + MMA: 4 j-pairs
            #pragma unroll
            for (int jp = 0; jp < 4; jp++) {
                int r = wn * 64 + (jp * 2 + b_jsel) * 8 + b_row;
                int k = ks * 16 + b_kh * 8;
                u32 b[4];
                ldsm4(Boff + (u32)(r * 128 + ((((k >> 3) ^ (r & 7))) << 4)), b);
                #pragma unroll
                for (int i = 0; i < 2; i++) {
                    mma16816(acc[i][jp * 2],     a[i], b[0], b[1]);
                    mma16816(acc[i][jp * 2 + 1], a[i], b[2], b[3]);
                }
            }
        }
        if (c + 1 < NCH) asm volatile("cp.async.wait_group 0;" ::: "memory");
        __syncthreads();
    }

    // denominator reduce (fp32 exact): 4 k-quarter partials per row
    den_s[tid] = den;
    __syncthreads();
    if (tid < 128) {
        float s = den_s[tid] + den_s[tid + 128] + den_s[tid + 256] + den_s[tid + 384];
        g_den[split][b0p + tid] = s;
    }

    // epilogue: accumulators -> g_num
    #pragma unroll
    for (int i = 0; i < 2; i++) {
        int m = b0p + wm * 32 + i * 16 + g;
        #pragma unroll
        for (int j = 0; j < 8; j++) {
            int col = wn * 64 + j * 8 + tig * 2;
            *(float2*)&g_num[split][m][col]     = make_float2(acc[i][j][0], acc[i][j][1]);
            *(float2*)&g_num[split][m + 8][col] = make_float2(acc[i][j][2], acc[i][j][3]);
        }
    }
}

// ---------------- kernel 4: denominator reduce ----------------
__global__ void k_den()
{
    int b = blockIdx.x * blockDim.x + threadIdx.x;
    if (b < B_PAT) {
        float s = 0.0f;
        #pragma unroll
        for (int i = 0; i < NSK; i++) s += g_den[i][b];
        g_invden[b] = 1.0f / s;
    }
}

// ---------------- kernel 5: finalize out = pf + num * invden ----------------
__global__ void k_fin(const float* __restrict__ pf, float* __restrict__ out)
{
    int idx = blockIdx.x * blockDim.x + threadIdx.x;
    if (idx >= B_PAT * DIM / 4) return;
    int b = idx >> 6;
    float4 p = ((const float4*)pf)[idx];
    float4 s = make_float4(0.f, 0.f, 0.f, 0.f);
    const float4* num4 = (const float4*)g_num;
    #pragma unroll
    for (int i = 0; i < NSK; i++) {
        float4 v = num4[(size_t)i * (B_PAT * DIM / 4) + idx];
        s.x += v.x; s.y += v.y; s.z += v.z; s.w += v.w;
    }
    float inv = g_invden[b];
    float4 o;
    o.x = p.x + s.x * inv;  o.y = p.y + s.y * inv;
    o.z = p.z + s.z * inv;  o.w = p.w + s.w * inv;
    ((float4*)out)[idx] = o;
}

// ---------------- launch ----------------
extern "C" void kernel_launch(void* const* d_in, const int* in_sizes, int n_in,
                              void* d_out, int out_size)
{
    const float* pf = (const float*)d_in[0];
    const float* dn = (const float*)d_in[1];
    const float* ak = (const float*)d_in[2];
    float* out = (float*)d_out;

    static int configured = 0;
    if (!configured) {
        cudaFuncSetAttribute(k_main, cudaFuncAttributeMaxDynamicSharedMemorySize, SMEM_TOTAL);
        configured = 1;
    }

    k_init<<<1, 1>>>();
    k_cvt<<<dim3(NPAD / 64, DIM / 64), 256>>>(dn);
    k_scores<<<(B_PAT + N_DIS) / 8, 256>>>(pf, dn, ak);
    k_main<<<dim3(PT, NSK), NTHR, SMEM_TOTAL>>>();
    k_den<<<(B_PAT + 255) / 256, 256>>>();
    k_fin<<<(B_PAT * DIM / 4 + 255) / 256, 256>>>(pf, out);
}